// round 13
// baseline (speedup 1.0000x reference)
#include <cuda_runtime.h>
#include <cuda_fp16.h>

#define HH 512
#define WW 512
#define CC 128
#define NPTS 524288
#define PLANE_ELEMS (CC * HH * WW)

#define THALF_BLOCKS (2 * HH * (WW / 32))  // 16384
#define SETUP_BLOCKS (NPTS / 256)          // 2048
#define PASS_BLOCKS (NPTS / 32)            // 16384

#define NSM 152
#define KCAP 4608              // bin capacity (mean ~3449, +10 sigma)
#define K3_BLOCKS (NSM * 5)    // one wave: 5 blocks/SM
#define SPILL_CAP 8192

// Transposed fp16 planes [H][W][C] (channel-last).
__device__ __align__(16) __half g_uvT[PLANE_ELEMS];
__device__ __align__(16) __half g_stT[PLANE_ELEMS];
// Linear 16B record (for k2): {uvBase, stBase, h2(wxu,wyu), h2(wxs,wys)}
__device__ __align__(16) uint4 g_rec[NPTS];
// fp16 partials from pass A.
__device__ __align__(16) uint4 g_part[NPTS];
// Binned 16B records for k3: {uvTexel|pidLo<<18, stTexel|pidHi<<18, wuv, wst}
__device__ __align__(16) uint4 g_binrec[NSM * KCAP];
__device__ __align__(128) int g_bcnt[NSM * 32];
__device__ __align__(128) int g_spillcnt[32];
__device__ __align__(16) uint4 g_sprec[SPILL_CAP];

__device__ __forceinline__ unsigned packw2(float a, float b) {
    __half2 h = __floats2half2_rn(a, b);
    return *(unsigned*)&h;
}
__device__ __forceinline__ __half2 u2h(unsigned u) { return *(__half2*)&u; }

// ---------------------------------------------------------------------------
// Kernel 0: zero bin/spill counters (graph replays rerun the atomics).
// ---------------------------------------------------------------------------
__global__ void zero_kernel() {
    for (int i = threadIdx.x; i < NSM * 32; i += 256) g_bcnt[i] = 0;
    if (threadIdx.x == 0) g_spillcnt[0] = 0;
}

// ---------------------------------------------------------------------------
// Half-channel transpose tile: [C,H,W] f32 -> [H,W,C] f16 for 64 channels.
// ---------------------------------------------------------------------------
template <int CHOFF, bool STREAM>
__device__ __forceinline__ void transpose_half(
    int tbid, int tid, const float* __restrict__ uv,
    const float* __restrict__ st) {
    __shared__ float tile[64][33];
    const int plane = tbid >> 13;
    const int rem = tbid & 8191;
    const int y = rem >> 4;
    const int x0 = (rem & 15) * 32;
    const int tx = tid & 31;
    const int ty = tid >> 5;

    const float* src = plane ? st : uv;
    __half* dst = plane ? g_stT : g_uvT;

    #pragma unroll
    for (int i = 0; i < 8; i++) {
        const int c = ty + i * 8;
        const float* sp = &src[(size_t)(CHOFF + c) * (HH * WW) + y * WW + x0 + tx];
        tile[c][tx] = STREAM ? __ldcs(sp) : *sp;
    }
    __syncthreads();

    const int c2 = (tid & 31) * 2;
    const int xb = tid >> 5;
    #pragma unroll
    for (int i = 0; i < 4; i++) {
        const int xi = xb + i * 8;
        __half2 v = __floats2half2_rn(tile[c2][xi], tile[c2 + 1][xi]);
        __half2* dp = (__half2*)(dst + (size_t)(y * WW + x0 + xi) * CC + CHOFF + c2);
        if (STREAM) __stcs((uint*)dp, *(uint*)&v);
        else *dp = v;
    }
}

// ---------------------------------------------------------------------------
// Pass A body (ch 0-63): 8 lanes/point, writes fp16 partials.
// ---------------------------------------------------------------------------
__device__ __forceinline__ void passA_body(int pbid, int tid) {
    const int p = pbid * 32 + (tid >> 3);
    const int gl = tid & 7;

    const uint4 r = __ldcs(&g_rec[p]);

    const __half* U = g_uvT + r.x + gl * 8;
    const __half* S = g_stT + r.y + gl * 8;

    const uint4 u00 = *(const uint4*)(U);
    const uint4 u01 = *(const uint4*)(U + CC);
    const uint4 u10 = *(const uint4*)(U + WW * CC);
    const uint4 u11 = *(const uint4*)(U + WW * CC + CC);
    const uint4 s00 = *(const uint4*)(S);
    const uint4 s01 = *(const uint4*)(S + CC);
    const uint4 s10 = *(const uint4*)(S + WW * CC);
    const uint4 s11 = *(const uint4*)(S + WW * CC + CC);

    const __half2 one = __float2half2_rn(1.f);
    __half2 au[4], av[4];
    {
        const __half2 h = u2h(r.z);
        const __half2 wx = __low2half2(h), wy = __high2half2(h);
        const __half2 ix = __hsub2(one, wx), iy = __hsub2(one, wy);
        const __half2 w00 = __hmul2(ix, iy), w01 = __hmul2(wx, iy);
        const __half2 w10 = __hmul2(ix, wy), w11 = __hmul2(wx, wy);
        const __half2* p00 = (const __half2*)&u00;
        const __half2* p01 = (const __half2*)&u01;
        const __half2* p10 = (const __half2*)&u10;
        const __half2* p11 = (const __half2*)&u11;
        #pragma unroll
        for (int j = 0; j < 4; j++) {
            __half2 a = __hmul2(p00[j], w00);
            a = __hfma2(p01[j], w01, a);
            a = __hfma2(p10[j], w10, a);
            au[j] = __hfma2(p11[j], w11, a);
        }
    }
    {
        const __half2 h = u2h(r.w);
        const __half2 wx = __low2half2(h), wy = __high2half2(h);
        const __half2 ix = __hsub2(one, wx), iy = __hsub2(one, wy);
        const __half2 w00 = __hmul2(ix, iy), w01 = __hmul2(wx, iy);
        const __half2 w10 = __hmul2(ix, wy), w11 = __hmul2(wx, wy);
        const __half2* p00 = (const __half2*)&s00;
        const __half2* p01 = (const __half2*)&s01;
        const __half2* p10 = (const __half2*)&s10;
        const __half2* p11 = (const __half2*)&s11;
        #pragma unroll
        for (int j = 0; j < 4; j++) {
            __half2 a = __hmul2(p00[j], w00);
            a = __hfma2(p01[j], w01, a);
            a = __hfma2(p10[j], w10, a);
            av[j] = __hfma2(p11[j], w11, a);
        }
    }

    float f[8];
    #pragma unroll
    for (int j = 0; j < 4; j++) {
        const float2 t = __half22float2(__hmul2(au[j], av[j]));
        f[2 * j] = t.x;
        f[2 * j + 1] = t.y;
    }
    #pragma unroll
    for (int s = 4; s >= 1; s >>= 1) {
        #pragma unroll
        for (int j = 0; j < 8; j++)
            f[j] += __shfl_xor_sync(0xffffffffu, f[j], s);
    }

    if (gl == 0) {
        uint4 pk;
        pk.x = packw2(f[0], f[1]);
        pk.y = packw2(f[2], f[3]);
        pk.z = packw2(f[4], f[5]);
        pk.w = packw2(f[6], f[7]);
        __stcs(&g_part[p], pk);
    }
}

// ---------------------------------------------------------------------------
// k3 point body (ch 64-127): binned rec; uv cached in L1, st streamed.
// ---------------------------------------------------------------------------
__device__ __forceinline__ void k3_point(const uint4 r, int gl,
                                         float* __restrict__ out) {
    const unsigned uvT = r.x & 0x3FFFFu;
    const unsigned stT = r.y & 0x3FFFFu;
    const int pid = (int)((r.x >> 18) | ((r.y >> 18) << 14));

    const __half* U = g_uvT + (size_t)uvT * CC + 64 + gl * 8;
    const __half* S = g_stT + (size_t)stT * CC + 64 + gl * 8;

    // uv: default caching (bin window ~L1-resident via SM affinity).
    const uint4 u00 = *(const uint4*)(U);
    const uint4 u01 = *(const uint4*)(U + CC);
    const uint4 u10 = *(const uint4*)(U + WW * CC);
    const uint4 u11 = *(const uint4*)(U + WW * CC + CC);
    // st: random — stream so it doesn't evict the uv window.
    const uint4 s00 = __ldcs((const uint4*)(S));
    const uint4 s01 = __ldcs((const uint4*)(S + CC));
    const uint4 s10 = __ldcs((const uint4*)(S + WW * CC));
    const uint4 s11 = __ldcs((const uint4*)(S + WW * CC + CC));

    const __half2 one = __float2half2_rn(1.f);
    __half2 au[4], av[4];
    {
        const __half2 h = u2h(r.z);
        const __half2 wx = __low2half2(h), wy = __high2half2(h);
        const __half2 ix = __hsub2(one, wx), iy = __hsub2(one, wy);
        const __half2 w00 = __hmul2(ix, iy), w01 = __hmul2(wx, iy);
        const __half2 w10 = __hmul2(ix, wy), w11 = __hmul2(wx, wy);
        const __half2* p00 = (const __half2*)&u00;
        const __half2* p01 = (const __half2*)&u01;
        const __half2* p10 = (const __half2*)&u10;
        const __half2* p11 = (const __half2*)&u11;
        #pragma unroll
        for (int j = 0; j < 4; j++) {
            __half2 a = __hmul2(p00[j], w00);
            a = __hfma2(p01[j], w01, a);
            a = __hfma2(p10[j], w10, a);
            au[j] = __hfma2(p11[j], w11, a);
        }
    }
    {
        const __half2 h = u2h(r.w);
        const __half2 wx = __low2half2(h), wy = __high2half2(h);
        const __half2 ix = __hsub2(one, wx), iy = __hsub2(one, wy);
        const __half2 w00 = __hmul2(ix, iy), w01 = __hmul2(wx, iy);
        const __half2 w10 = __hmul2(ix, wy), w11 = __hmul2(wx, wy);
        const __half2* p00 = (const __half2*)&s00;
        const __half2* p01 = (const __half2*)&s01;
        const __half2* p10 = (const __half2*)&s10;
        const __half2* p11 = (const __half2*)&s11;
        #pragma unroll
        for (int j = 0; j < 4; j++) {
            __half2 a = __hmul2(p00[j], w00);
            a = __hfma2(p01[j], w01, a);
            a = __hfma2(p10[j], w10, a);
            av[j] = __hfma2(p11[j], w11, a);
        }
    }

    float f[8];
    #pragma unroll
    for (int j = 0; j < 4; j++) {
        const float2 t = __half22float2(__hmul2(au[j], av[j]));
        f[2 * j] = t.x;
        f[2 * j + 1] = t.y;
    }
    #pragma unroll
    for (int s = 4; s >= 1; s >>= 1) {
        #pragma unroll
        for (int j = 0; j < 8; j++)
            f[j] += __shfl_xor_sync(0xffffffffu, f[j], s);
    }

    if (gl == 0) {
        const uint4 pk = __ldcs(&g_part[pid]);
        const float2 a0 = __half22float2(u2h(pk.x));
        const float2 a1 = __half22float2(u2h(pk.y));
        const float2 a2 = __half22float2(u2h(pk.z));
        const float2 a3 = __half22float2(u2h(pk.w));
        float4 o0, o1;
        o0.x = 1.f / (1.f + __expf(-(f[0] + a0.x)));
        o0.y = 1.f / (1.f + __expf(-(f[1] + a0.y)));
        o0.z = 1.f / (1.f + __expf(-(f[2] + a1.x)));
        o0.w = 1.f / (1.f + __expf(-(f[3] + a1.y)));
        o1.x = 1.f / (1.f + __expf(-(f[4] + a2.x)));
        o1.y = 1.f / (1.f + __expf(-(f[5] + a2.y)));
        o1.z = 1.f / (1.f + __expf(-(f[6] + a3.x)));
        o1.w = 1.f / (1.f + __expf(-(f[7] + a3.y)));
        __stcs(&((float4*)out)[pid * 2], o0);
        __stcs(&((float4*)out)[pid * 2 + 1], o1);
    }
}

// ---------------------------------------------------------------------------
// K1: transpose ch 0-63 + setup (linear rec for k2, binned rec for k3).
// ---------------------------------------------------------------------------
__global__ __launch_bounds__(256) void k1_kernel(
    const float* __restrict__ uv, const float* __restrict__ st,
    const float4* __restrict__ xs, const float* __restrict__ b) {
    const int bid = blockIdx.x;
    const int tid = threadIdx.x;

    if (bid < THALF_BLOCKS) {
        transpose_half<0, false>(bid, tid, uv, st);
    } else {
        const int i = (bid - THALF_BLOCKS) * 256 + tid;
        const float4 p = __ldcs(&xs[i]);

        const float ixu = __fdividef(p.x - b[0], b[4] - b[0]) * (WW - 1);
        const float iyu = __fdividef(p.y - b[1], b[5] - b[1]) * (HH - 1);
        const float ixs = __fdividef(p.z - b[2], b[6] - b[2]) * (WW - 1);
        const float iys = __fdividef(p.w - b[3], b[7] - b[3]) * (HH - 1);

        const int xu0 = min(max(__float2int_rd(ixu), 0), WW - 2);
        const int yu0 = min(max(__float2int_rd(iyu), 0), HH - 2);
        const int xs0 = min(max(__float2int_rd(ixs), 0), WW - 2);
        const int ys0 = min(max(__float2int_rd(iys), 0), HH - 2);

        const unsigned wuv = packw2(ixu - (float)xu0, iyu - (float)yu0);
        const unsigned wst = packw2(ixs - (float)xs0, iys - (float)ys0);
        const unsigned uvTex = (unsigned)(yu0 * WW + xu0);
        const unsigned stTex = (unsigned)(ys0 * WW + xs0);

        uint4 r;
        r.x = uvTex * CC;
        r.y = stTex * CC;
        r.z = wuv;
        r.w = wst;
        g_rec[i] = r;

        // Binned record for k3: 19 y-strips x 8 x-strips = 152 bins.
        const int bin = ((yu0 * 19) >> 9) * 8 + (xu0 >> 6);
        uint4 br;
        br.x = uvTex | (((unsigned)i & 0x3FFFu) << 18);
        br.y = stTex | (((unsigned)i >> 14) << 18);
        br.z = wuv;
        br.w = wst;
        const int slot = atomicAdd(&g_bcnt[bin * 32], 1);
        if (slot < KCAP) {
            g_binrec[bin * KCAP + slot] = br;
        } else {
            const int s = atomicAdd(&g_spillcnt[0], 1);
            if (s < SPILL_CAP) g_sprec[s] = br;
        }
    }
}

// ---------------------------------------------------------------------------
// K2 (fused): passA (ch 0-63) || transpose ch 64-127.  (unchanged from R12)
// ---------------------------------------------------------------------------
__global__ __launch_bounds__(256) void k2_kernel(
    const float* __restrict__ uv, const float* __restrict__ st,
    float* __restrict__ out) {
    const int bid = blockIdx.x;
    const int tid = threadIdx.x;
    if (bid & 1) {
        transpose_half<64, true>(bid >> 1, tid, uv, st);
    } else {
        passA_body(bid >> 1, tid);
    }
}

// ---------------------------------------------------------------------------
// K3: one-wave cluster kernel. bin = bid % NSM -> with CLC contiguous-modular
// placement, the 5 blocks of a bin land on ONE SM -> uv window L1-resident.
// ---------------------------------------------------------------------------
__global__ __launch_bounds__(256) void k3_kernel(float* __restrict__ out) {
    const int tid = threadIdx.x;
    const int g = tid >> 3;
    const int gl = tid & 7;
    const int bin = blockIdx.x % NSM;
    const int q = blockIdx.x / NSM;  // 0..4

    const int cnt = min(g_bcnt[bin * 32], KCAP);
    const int per = (cnt + 4) / 5;
    const int lo = q * per;
    const int hi = min(lo + per, cnt);
    const uint4* base = &g_binrec[bin * KCAP];

    int i = lo + g;
    uint4 r;
    if (i < hi) r = __ldcs(&base[i]);
    while (i < hi) {
        const int nx = i + 32;
        uint4 rn = r;
        if (nx < hi) rn = __ldcs(&base[nx]);
        k3_point(r, gl, out);
        r = rn;
        i = nx;
    }

    // Spill (normally empty).
    const int sn = min(g_spillcnt[0], SPILL_CAP);
    for (int s = blockIdx.x * 32 + g; s < sn; s += K3_BLOCKS * 32)
        k3_point(g_sprec[s], gl, out);
}

// ---------------------------------------------------------------------------
extern "C" void kernel_launch(void* const* d_in, const int* in_sizes, int n_in,
                              void* d_out, int out_size) {
    const float* x = (const float*)d_in[0];
    const float* uv = (const float*)d_in[1];
    const float* st = (const float*)d_in[2];
    const float* bounds = (const float*)d_in[3];
    float* out = (float*)d_out;

    cudaFuncSetAttribute(k3_kernel,
                         cudaFuncAttributePreferredSharedMemoryCarveout, 0);

    zero_kernel<<<1, 256>>>();
    k1_kernel<<<THALF_BLOCKS + SETUP_BLOCKS, 256>>>(
        uv, st, (const float4*)x, bounds);
    k2_kernel<<<THALF_BLOCKS + PASS_BLOCKS, 256>>>(uv, st, out);

    // Cluster launch (cluster=2) to get CLC contiguous-modular placement.
    cudaLaunchConfig_t cfg = {};
    cfg.gridDim = dim3(K3_BLOCKS, 1, 1);
    cfg.blockDim = dim3(256, 1, 1);
    cudaLaunchAttribute attrs[1];
    attrs[0].id = cudaLaunchAttributeClusterDimension;
    attrs[0].val.clusterDim = {2, 1, 1};
    cfg.attrs = attrs;
    cfg.numAttrs = 1;
    cudaError_t e = cudaLaunchKernelEx(&cfg, k3_kernel, out);
    if (e != cudaSuccess) {
        k3_kernel<<<K3_BLOCKS, 256>>>(out);  // fallback: plain launch
    }
}

// round 14
// speedup vs baseline: 1.1741x; 1.1741x over previous
#include <cuda_runtime.h>
#include <cuda_fp16.h>

#define HH 512
#define WW 512
#define CC 128
#define NPTS 524288
#define PLANE_ELEMS (CC * HH * WW)

#define THALF_BLOCKS (2 * HH * (WW / 32))  // 16384
#define SETUP_BLOCKS (NPTS / 256)          // 2048
#define PASS_BLOCKS (NPTS / 32)            // 16384

#define NBIN2 16384   // 128 x 128 grid of 4x4-texel uv tiles
#define HPAD 8        // 32B padding per counter (4 bins per L2 line)

// Transposed fp16 planes [H][W][C] (channel-last).
__device__ __align__(16) __half g_uvT[PLANE_ELEMS];
__device__ __align__(16) __half g_stT[PLANE_ELEMS];
// 16B records: {uvTex | pidLo<<18, stTex | pidHi<<18, h2(wxu,wyu), h2(wxs,wys)}
__device__ __align__(16) uint4 g_rec[NPTS];    // unsorted (point order)
__device__ __align__(16) uint4 g_srec[NPTS];   // uv-tile-sorted
// fp16 partials from pass A (indexed by sorted slot).
__device__ __align__(16) uint4 g_part[NPTS];
__device__ __align__(128) int g_hist[NBIN2 * HPAD];
__device__ __align__(128) int g_cursor[NBIN2 * HPAD];

__device__ __forceinline__ unsigned packw2(float a, float b) {
    __half2 h = __floats2half2_rn(a, b);
    return *(unsigned*)&h;
}
__device__ __forceinline__ __half2 u2h(unsigned u) { return *(__half2*)&u; }

// ---------------------------------------------------------------------------
// Kernel 0: zero the padded histogram (graph replays rerun the REDs).
// ---------------------------------------------------------------------------
__global__ void zero_kernel() {
    g_hist[blockIdx.x * 256 + threadIdx.x] = 0;
}

// ---------------------------------------------------------------------------
// Half-channel transpose tile: [C,H,W] f32 -> [H,W,C] f16 for 64 channels.
// ---------------------------------------------------------------------------
template <int CHOFF, bool STREAM>
__device__ __forceinline__ void transpose_half(
    int tbid, int tid, const float* __restrict__ uv,
    const float* __restrict__ st) {
    __shared__ float tile[64][33];
    const int plane = tbid >> 13;
    const int rem = tbid & 8191;
    const int y = rem >> 4;
    const int x0 = (rem & 15) * 32;
    const int tx = tid & 31;
    const int ty = tid >> 5;

    const float* src = plane ? st : uv;
    __half* dst = plane ? g_stT : g_uvT;

    #pragma unroll
    for (int i = 0; i < 8; i++) {
        const int c = ty + i * 8;
        const float* sp = &src[(size_t)(CHOFF + c) * (HH * WW) + y * WW + x0 + tx];
        tile[c][tx] = STREAM ? __ldcs(sp) : *sp;
    }
    __syncthreads();

    const int c2 = (tid & 31) * 2;
    const int xb = tid >> 5;
    #pragma unroll
    for (int i = 0; i < 4; i++) {
        const int xi = xb + i * 8;
        __half2 v = __floats2half2_rn(tile[c2][xi], tile[c2 + 1][xi]);
        __half2* dp = (__half2*)(dst + (size_t)(y * WW + x0 + xi) * CC + CHOFF + c2);
        if (STREAM) __stcs((uint*)dp, *(uint*)&v);
        else *dp = v;
    }
}

// ---------------------------------------------------------------------------
// Pass body: 8 lanes/point, lane gl = channels CHOFF+8*gl (uint4/corner).
// Reads SORTED records; partials slot-indexed; final store scattered by pid.
// ---------------------------------------------------------------------------
template <int CHOFF, bool FIRST>
__device__ __forceinline__ void pass_body(int pbid, int tid,
                                          float* __restrict__ out) {
    const int p = pbid * 32 + (tid >> 3);  // sorted slot
    const int gl = tid & 7;

    const uint4 r = __ldcs(&g_srec[p]);
    const unsigned uvTex = r.x & 0x3FFFFu;
    const unsigned stTex = r.y & 0x3FFFFu;

    const __half* U = g_uvT + (size_t)uvTex * CC + CHOFF + gl * 8;
    const __half* S = g_stT + (size_t)stTex * CC + CHOFF + gl * 8;

    const uint4 u00 = *(const uint4*)(U);
    const uint4 u01 = *(const uint4*)(U + CC);
    const uint4 u10 = *(const uint4*)(U + WW * CC);
    const uint4 u11 = *(const uint4*)(U + WW * CC + CC);
    const uint4 s00 = *(const uint4*)(S);
    const uint4 s01 = *(const uint4*)(S + CC);
    const uint4 s10 = *(const uint4*)(S + WW * CC);
    const uint4 s11 = *(const uint4*)(S + WW * CC + CC);

    const __half2 one = __float2half2_rn(1.f);
    __half2 au[4], av[4];
    {
        const __half2 h = u2h(r.z);
        const __half2 wx = __low2half2(h), wy = __high2half2(h);
        const __half2 ix = __hsub2(one, wx), iy = __hsub2(one, wy);
        const __half2 w00 = __hmul2(ix, iy), w01 = __hmul2(wx, iy);
        const __half2 w10 = __hmul2(ix, wy), w11 = __hmul2(wx, wy);
        const __half2* p00 = (const __half2*)&u00;
        const __half2* p01 = (const __half2*)&u01;
        const __half2* p10 = (const __half2*)&u10;
        const __half2* p11 = (const __half2*)&u11;
        #pragma unroll
        for (int j = 0; j < 4; j++) {
            __half2 a = __hmul2(p00[j], w00);
            a = __hfma2(p01[j], w01, a);
            a = __hfma2(p10[j], w10, a);
            au[j] = __hfma2(p11[j], w11, a);
        }
    }
    {
        const __half2 h = u2h(r.w);
        const __half2 wx = __low2half2(h), wy = __high2half2(h);
        const __half2 ix = __hsub2(one, wx), iy = __hsub2(one, wy);
        const __half2 w00 = __hmul2(ix, iy), w01 = __hmul2(wx, iy);
        const __half2 w10 = __hmul2(ix, wy), w11 = __hmul2(wx, wy);
        const __half2* p00 = (const __half2*)&s00;
        const __half2* p01 = (const __half2*)&s01;
        const __half2* p10 = (const __half2*)&s10;
        const __half2* p11 = (const __half2*)&s11;
        #pragma unroll
        for (int j = 0; j < 4; j++) {
            __half2 a = __hmul2(p00[j], w00);
            a = __hfma2(p01[j], w01, a);
            a = __hfma2(p10[j], w10, a);
            av[j] = __hfma2(p11[j], w11, a);
        }
    }

    float f[8];
    #pragma unroll
    for (int j = 0; j < 4; j++) {
        const float2 t = __half22float2(__hmul2(au[j], av[j]));
        f[2 * j] = t.x;
        f[2 * j + 1] = t.y;
    }
    #pragma unroll
    for (int s = 4; s >= 1; s >>= 1) {
        #pragma unroll
        for (int j = 0; j < 8; j++)
            f[j] += __shfl_xor_sync(0xffffffffu, f[j], s);
    }

    if (gl == 0) {
        if (FIRST) {
            uint4 pk;
            pk.x = packw2(f[0], f[1]);
            pk.y = packw2(f[2], f[3]);
            pk.z = packw2(f[4], f[5]);
            pk.w = packw2(f[6], f[7]);
            __stcs(&g_part[p], pk);
        } else {
            const uint4 pk = __ldcs(&g_part[p]);
            const float2 a0 = __half22float2(u2h(pk.x));
            const float2 a1 = __half22float2(u2h(pk.y));
            const float2 a2 = __half22float2(u2h(pk.z));
            const float2 a3 = __half22float2(u2h(pk.w));
            const int pid = (int)((r.x >> 18) | ((r.y >> 18) << 14));
            float4 o0, o1;
            o0.x = 1.f / (1.f + __expf(-(f[0] + a0.x)));
            o0.y = 1.f / (1.f + __expf(-(f[1] + a0.y)));
            o0.z = 1.f / (1.f + __expf(-(f[2] + a1.x)));
            o0.w = 1.f / (1.f + __expf(-(f[3] + a1.y)));
            o1.x = 1.f / (1.f + __expf(-(f[4] + a2.x)));
            o1.y = 1.f / (1.f + __expf(-(f[5] + a2.y)));
            o1.z = 1.f / (1.f + __expf(-(f[6] + a3.x)));
            o1.w = 1.f / (1.f + __expf(-(f[7] + a3.y)));
            __stcs(&((float4*)out)[pid * 2], o0);
            __stcs(&((float4*)out)[pid * 2 + 1], o1);
        }
    }
}

// ---------------------------------------------------------------------------
// K1: transpose ch 0-63 + setup (record + histogram RED).
// ---------------------------------------------------------------------------
__global__ __launch_bounds__(256) void k1_kernel(
    const float* __restrict__ uv, const float* __restrict__ st,
    const float4* __restrict__ xs, const float* __restrict__ b) {
    const int bid = blockIdx.x;
    const int tid = threadIdx.x;

    if (bid < THALF_BLOCKS) {
        transpose_half<0, false>(bid, tid, uv, st);
    } else {
        const int i = (bid - THALF_BLOCKS) * 256 + tid;
        const float4 p = __ldcs(&xs[i]);

        const float ixu = __fdividef(p.x - b[0], b[4] - b[0]) * (WW - 1);
        const float iyu = __fdividef(p.y - b[1], b[5] - b[1]) * (HH - 1);
        const float ixs = __fdividef(p.z - b[2], b[6] - b[2]) * (WW - 1);
        const float iys = __fdividef(p.w - b[3], b[7] - b[3]) * (HH - 1);

        const int xu0 = min(max(__float2int_rd(ixu), 0), WW - 2);
        const int yu0 = min(max(__float2int_rd(iyu), 0), HH - 2);
        const int xs0 = min(max(__float2int_rd(ixs), 0), WW - 2);
        const int ys0 = min(max(__float2int_rd(iys), 0), HH - 2);

        const unsigned uvTex = (unsigned)(yu0 * WW + xu0);
        const unsigned stTex = (unsigned)(ys0 * WW + xs0);

        uint4 r;
        r.x = uvTex | (((unsigned)i & 0x3FFFu) << 18);
        r.y = stTex | (((unsigned)i >> 14) << 18);
        r.z = packw2(ixu - (float)xu0, iyu - (float)yu0);
        r.w = packw2(ixs - (float)xs0, iys - (float)ys0);
        g_rec[i] = r;

        const int key = (yu0 >> 2) * 128 + (xu0 >> 2);  // 4x4 tiles
        atomicAdd(&g_hist[key * HPAD], 1);              // RED, padded
    }
}

// ---------------------------------------------------------------------------
// Scan: exclusive prefix over 16384 bins. One block, 1024 threads x 16 bins.
// ---------------------------------------------------------------------------
__global__ __launch_bounds__(1024) void scan_kernel() {
    __shared__ int warptot[32];
    const int t = threadIdx.x;
    const int lane = t & 31, wid = t >> 5;

    int local[16];
    int sum = 0;
    #pragma unroll
    for (int j = 0; j < 16; j++) {
        local[j] = sum;
        sum += g_hist[(t * 16 + j) * HPAD];
    }

    // Inclusive warp scan of per-thread sums.
    int v = sum;
    #pragma unroll
    for (int d = 1; d < 32; d <<= 1) {
        const int u = __shfl_up_sync(0xffffffffu, v, d);
        if (lane >= d) v += u;
    }
    if (lane == 31) warptot[wid] = v;
    __syncthreads();
    if (wid == 0) {
        int w = warptot[lane];
        #pragma unroll
        for (int d = 1; d < 32; d <<= 1) {
            const int u = __shfl_up_sync(0xffffffffu, w, d);
            if (lane >= d) w += u;
        }
        warptot[lane] = w;
    }
    __syncthreads();

    const int base = ((wid > 0) ? warptot[wid - 1] : 0) + (v - sum);
    #pragma unroll
    for (int j = 0; j < 16; j++)
        g_cursor[(t * 16 + j) * HPAD] = base + local[j];
}

// ---------------------------------------------------------------------------
// Scatter: 16B records into sorted order (per-point atomic on padded cursor).
// ---------------------------------------------------------------------------
__global__ __launch_bounds__(256) void scatter_kernel() {
    const int i = blockIdx.x * 256 + threadIdx.x;
    const uint4 r = g_rec[i];
    const unsigned tex = r.x & 0x3FFFFu;
    const int y0 = (int)(tex >> 9), x0 = (int)(tex & 511);
    const int key = (y0 >> 2) * 128 + (x0 >> 2);
    const int dst = atomicAdd(&g_cursor[key * HPAD], 1);
    g_srec[dst] = r;
}

// ---------------------------------------------------------------------------
// K2 (fused): passA (ch 0-63) || transpose ch 64-127.
// ---------------------------------------------------------------------------
__global__ __launch_bounds__(256) void k2_kernel(
    const float* __restrict__ uv, const float* __restrict__ st,
    float* __restrict__ out) {
    const int bid = blockIdx.x;
    const int tid = threadIdx.x;
    if (bid & 1) {
        transpose_half<64, true>(bid >> 1, tid, uv, st);
    } else {
        pass_body<0, true>(bid >> 1, tid, out);
    }
}

// ---------------------------------------------------------------------------
// K3: passB (ch 64-127) + combine + sigmoid + scattered store by pid.
// ---------------------------------------------------------------------------
__global__ __launch_bounds__(256) void k3_kernel(float* __restrict__ out) {
    pass_body<64, false>(blockIdx.x, threadIdx.x, out);
}

// ---------------------------------------------------------------------------
extern "C" void kernel_launch(void* const* d_in, const int* in_sizes, int n_in,
                              void* d_out, int out_size) {
    const float* x = (const float*)d_in[0];
    const float* uv = (const float*)d_in[1];
    const float* st = (const float*)d_in[2];
    const float* bounds = (const float*)d_in[3];
    float* out = (float*)d_out;

    zero_kernel<<<(NBIN2 * HPAD) / 256, 256>>>();
    k1_kernel<<<THALF_BLOCKS + SETUP_BLOCKS, 256>>>(
        uv, st, (const float4*)x, bounds);
    scan_kernel<<<1, 1024>>>();
    scatter_kernel<<<NPTS / 256, 256>>>();
    k2_kernel<<<THALF_BLOCKS + PASS_BLOCKS, 256>>>(uv, st, out);
    k3_kernel<<<PASS_BLOCKS, 256>>>(out);
}

// round 15
// speedup vs baseline: 1.4357x; 1.2228x over previous
#include <cuda_runtime.h>
#include <cuda_fp16.h>

#define HH 512
#define WW 512
#define CC 128
#define NPTS 524288
#define PLANE_ELEMS (CC * HH * WW)

#define T64_BLOCKS (2 * HH * (WW / 64))   // 8192: 64-wide half-channel tiles
#define SETUP_BLOCKS (NPTS / 256)          // 2048
#define PASS_BLOCKS (NPTS / 32)            // 16384: 32 points/block, 8 lanes/pt
#define K2_BLOCKS (PASS_BLOCKS + T64_BLOCKS)  // 24576, 2:1 interleave

// Transposed fp16 planes [H][W][C] (channel-last).
__device__ __align__(16) __half g_uvT[PLANE_ELEMS];
__device__ __align__(16) __half g_stT[PLANE_ELEMS];
// 16B per-point record: {uvBase, stBase, h2(wxu,wyu), h2(wxs,wys)}
__device__ __align__(16) uint4 g_rec[NPTS];
// fp16 partials from pass A: 8 halfs per point (one uint4).
__device__ __align__(16) uint4 g_part[NPTS];

__device__ __forceinline__ unsigned packw2(float a, float b) {
    __half2 h = __floats2half2_rn(a, b);
    return *(unsigned*)&h;
}
__device__ __forceinline__ __half2 u2h(unsigned u) { return *(__half2*)&u; }

// ---------------------------------------------------------------------------
// 64-wide half-channel transpose tile: [C,H,W] f32 -> [H,W,C] f16, 64 ch.
// Each block: one y row, 64 x-texels, 64 channels. 16 in-flight loads/thread.
// STREAM=true uses evict-first hints (fused with a pass that owns L2).
// ---------------------------------------------------------------------------
template <int CHOFF, bool STREAM>
__device__ __forceinline__ void transpose64(
    int tbid, int tid, const float* __restrict__ uv,
    const float* __restrict__ st) {
    __shared__ float tile[64][65];
    const int plane = tbid >> 12;            // /4096
    const int rem = tbid & 4095;
    const int y = rem >> 3;
    const int x0 = (rem & 7) * 64;
    const int tx = tid & 31;
    const int wa = tid >> 5;  // 0..7

    const float* src = plane ? st : uv;
    __half* dst = plane ? g_stT : g_uvT;

    #pragma unroll
    for (int i = 0; i < 8; i++) {
        const int c = wa + i * 8;  // 0..63
        const float* sp = &src[(size_t)(CHOFF + c) * (HH * WW) + y * WW + x0 + tx];
        if (STREAM) {
            tile[c][tx] = __ldcs(sp);
            tile[c][tx + 32] = __ldcs(sp + 32);
        } else {
            tile[c][tx] = *sp;
            tile[c][tx + 32] = sp[32];
        }
    }
    __syncthreads();

    // Write: warp = fixed xi, lanes sweep channels -> one 128B line per store.
    const int c2 = tx * 2;  // 0..62
    #pragma unroll
    for (int i = 0; i < 8; i++) {
        const int xi = wa + i * 8;  // 0..63
        __half2 v = __floats2half2_rn(tile[c2][xi], tile[c2 + 1][xi]);
        __half2* dp = (__half2*)(dst + (size_t)(y * WW + x0 + xi) * CC + CHOFF + c2);
        if (STREAM) __stcs((uint*)dp, *(uint*)&v);
        else *dp = v;
    }
}

// ---------------------------------------------------------------------------
// Per-point bilinear pass body: 8 lanes/point, lane gl = channels CHOFF+8*gl.
// Corner weights reconstructed in-register from packed (wx, wy).
// ---------------------------------------------------------------------------
template <int CHOFF, bool FIRST>
__device__ __forceinline__ void pass_body(int pbid, int tid,
                                          float* __restrict__ out) {
    const int p = pbid * 32 + (tid >> 3);
    const int gl = tid & 7;

    const uint4 r = __ldcs(&g_rec[p]);

    const __half* U = g_uvT + r.x + CHOFF + gl * 8;
    const __half* S = g_stT + r.y + CHOFF + gl * 8;

    const uint4 u00 = *(const uint4*)(U);
    const uint4 u01 = *(const uint4*)(U + CC);
    const uint4 u10 = *(const uint4*)(U + WW * CC);
    const uint4 u11 = *(const uint4*)(U + WW * CC + CC);
    const uint4 s00 = *(const uint4*)(S);
    const uint4 s01 = *(const uint4*)(S + CC);
    const uint4 s10 = *(const uint4*)(S + WW * CC);
    const uint4 s11 = *(const uint4*)(S + WW * CC + CC);

    const __half2 one = __float2half2_rn(1.f);

    __half2 au[4], av[4];
    {
        const __half2 h = u2h(r.z);  // (wxu, wyu)
        const __half2 wx = __low2half2(h), wy = __high2half2(h);
        const __half2 ix = __hsub2(one, wx), iy = __hsub2(one, wy);
        const __half2 w00 = __hmul2(ix, iy), w01 = __hmul2(wx, iy);
        const __half2 w10 = __hmul2(ix, wy), w11 = __hmul2(wx, wy);
        const __half2* p00 = (const __half2*)&u00;
        const __half2* p01 = (const __half2*)&u01;
        const __half2* p10 = (const __half2*)&u10;
        const __half2* p11 = (const __half2*)&u11;
        #pragma unroll
        for (int j = 0; j < 4; j++) {
            __half2 a = __hmul2(p00[j], w00);
            a = __hfma2(p01[j], w01, a);
            a = __hfma2(p10[j], w10, a);
            au[j] = __hfma2(p11[j], w11, a);
        }
    }
    {
        const __half2 h = u2h(r.w);  // (wxs, wys)
        const __half2 wx = __low2half2(h), wy = __high2half2(h);
        const __half2 ix = __hsub2(one, wx), iy = __hsub2(one, wy);
        const __half2 w00 = __hmul2(ix, iy), w01 = __hmul2(wx, iy);
        const __half2 w10 = __hmul2(ix, wy), w11 = __hmul2(wx, wy);
        const __half2* p00 = (const __half2*)&s00;
        const __half2* p01 = (const __half2*)&s01;
        const __half2* p10 = (const __half2*)&s10;
        const __half2* p11 = (const __half2*)&s11;
        #pragma unroll
        for (int j = 0; j < 4; j++) {
            __half2 a = __hmul2(p00[j], w00);
            a = __hfma2(p01[j], w01, a);
            a = __hfma2(p10[j], w10, a);
            av[j] = __hfma2(p11[j], w11, a);
        }
    }

    float f[8];
    #pragma unroll
    for (int j = 0; j < 4; j++) {
        const float2 t = __half22float2(__hmul2(au[j], av[j]));
        f[2 * j] = t.x;
        f[2 * j + 1] = t.y;
    }

    #pragma unroll
    for (int s = 4; s >= 1; s >>= 1) {
        #pragma unroll
        for (int j = 0; j < 8; j++)
            f[j] += __shfl_xor_sync(0xffffffffu, f[j], s);
    }

    if (gl == 0) {
        if (FIRST) {
            uint4 pk;
            pk.x = packw2(f[0], f[1]);
            pk.y = packw2(f[2], f[3]);
            pk.z = packw2(f[4], f[5]);
            pk.w = packw2(f[6], f[7]);
            __stcs(&g_part[p], pk);
        } else {
            const uint4 pk = __ldcs(&g_part[p]);
            const float2 a0 = __half22float2(u2h(pk.x));
            const float2 a1 = __half22float2(u2h(pk.y));
            const float2 a2 = __half22float2(u2h(pk.z));
            const float2 a3 = __half22float2(u2h(pk.w));
            float4 o0, o1;
            o0.x = 1.f / (1.f + __expf(-(f[0] + a0.x)));
            o0.y = 1.f / (1.f + __expf(-(f[1] + a0.y)));
            o0.z = 1.f / (1.f + __expf(-(f[2] + a1.x)));
            o0.w = 1.f / (1.f + __expf(-(f[3] + a1.y)));
            o1.x = 1.f / (1.f + __expf(-(f[4] + a2.x)));
            o1.y = 1.f / (1.f + __expf(-(f[5] + a2.y)));
            o1.z = 1.f / (1.f + __expf(-(f[6] + a3.x)));
            o1.w = 1.f / (1.f + __expf(-(f[7] + a3.y)));
            __stcs(&((float4*)out)[p * 2], o0);
            __stcs(&((float4*)out)[p * 2 + 1], o1);
        }
    }
}

// ---------------------------------------------------------------------------
// K1: transpose ch 0-63 (both planes, 64-wide tiles) + per-point setup.
// ---------------------------------------------------------------------------
__global__ __launch_bounds__(256) void k1_kernel(
    const float* __restrict__ uv, const float* __restrict__ st,
    const float4* __restrict__ xs, const float* __restrict__ b) {
    const int bid = blockIdx.x;
    const int tid = threadIdx.x;

    if (bid < T64_BLOCKS) {
        transpose64<0, false>(bid, tid, uv, st);
    } else {
        const int i = (bid - T64_BLOCKS) * 256 + tid;
        const float4 p = __ldcs(&xs[i]);

        const float ixu = __fdividef(p.x - b[0], b[4] - b[0]) * (WW - 1);
        const float iyu = __fdividef(p.y - b[1], b[5] - b[1]) * (HH - 1);
        const float ixs = __fdividef(p.z - b[2], b[6] - b[2]) * (WW - 1);
        const float iys = __fdividef(p.w - b[3], b[7] - b[3]) * (HH - 1);

        const int xu0 = min(max(__float2int_rd(ixu), 0), WW - 2);
        const int yu0 = min(max(__float2int_rd(iyu), 0), HH - 2);
        const int xs0 = min(max(__float2int_rd(ixs), 0), WW - 2);
        const int ys0 = min(max(__float2int_rd(iys), 0), HH - 2);

        uint4 r;
        r.x = (unsigned)((yu0 * WW + xu0) * CC);
        r.y = (unsigned)((ys0 * WW + xs0) * CC);
        r.z = packw2(ixu - (float)xu0, iyu - (float)yu0);
        r.w = packw2(ixs - (float)xs0, iys - (float)ys0);
        g_rec[i] = r;
    }
}

// ---------------------------------------------------------------------------
// K2 (fused): passA (ch 0-63, LTS-bound) || transpose ch 64-127 (DRAM-bound).
// 2:1 interleave (two pass blocks per transpose block).
// ---------------------------------------------------------------------------
__global__ __launch_bounds__(256) void k2_kernel(
    const float* __restrict__ uv, const float* __restrict__ st,
    float* __restrict__ out) {
    const int bid = blockIdx.x;
    const int tid = threadIdx.x;
    const int g = bid / 3;
    const int rr = bid - g * 3;
    if (rr == 2) {
        transpose64<64, true>(g, tid, uv, st);
    } else {
        pass_body<0, true>(g * 2 + rr, tid, out);
    }
}

// ---------------------------------------------------------------------------
// K3: passB (ch 64-127) + combine + sigmoid + store.
// ---------------------------------------------------------------------------
__global__ __launch_bounds__(256) void k3_kernel(float* __restrict__ out) {
    pass_body<64, false>(blockIdx.x, threadIdx.x, out);
}

// ---------------------------------------------------------------------------
extern "C" void kernel_launch(void* const* d_in, const int* in_sizes, int n_in,
                              void* d_out, int out_size) {
    const float* x = (const float*)d_in[0];
    const float* uv = (const float*)d_in[1];
    const float* st = (const float*)d_in[2];
    const float* bounds = (const float*)d_in[3];
    float* out = (float*)d_out;

    k1_kernel<<<T64_BLOCKS + SETUP_BLOCKS, 256>>>(
        uv, st, (const float4*)x, bounds);
    k2_kernel<<<K2_BLOCKS, 256>>>(uv, st, out);
    k3_kernel<<<PASS_BLOCKS, 256>>>(out);
}